// round 1
// baseline (speedup 1.0000x reference)
#include <cuda_runtime.h>
#include <cuda_bf16.h>

#define N_PTS   4096
#define NSAMPLE 9
#define TOPK    5
#define R2      0.01f      // RADIUS^2
#define H2      0.0144f    // H^2 = 0.12^2
#define EPS_    1e-12f
#define TPB     128
#define BLOCKS_PER_BATCH (N_PTS / TPB)   // 32

// fixed-order partial sums (deterministic reduction, no fp atomics)
__device__ float g_partials[1024];

__global__ void __launch_bounds__(TPB)
density_main(const float* __restrict__ pred) {
    // Batch point cache: float2 xy (32KB) + float z (16KB) = 48KB static (limit)
    __shared__ float2 sxy[N_PTS];
    __shared__ float  sz[N_PTS];

    const int b   = blockIdx.x / BLOCKS_PER_BATCH;
    const int blk = blockIdx.x % BLOCKS_PER_BATCH;
    const float* pb = pred + (size_t)b * N_PTS * 3;

    for (int i = threadIdx.x; i < N_PTS; i += TPB) {
        float x = pb[i * 3 + 0];
        float y = pb[i * 3 + 1];
        float z = pb[i * 3 + 2];
        sxy[i] = make_float2(x, y);
        sz[i]  = z;
    }
    __syncthreads();

    const int n = blk * TPB + threadIdx.x;
    const float2 q  = sxy[n];
    const float  qz = sz[n];

    float vals[NSAMPLE];
    int cnt = 0;

    // Sequential scan: first NSAMPLE in-ball points by ascending index.
    // Warp-wide early exit once every lane has NSAMPLE.
    for (int base = 0; base < N_PTS; base += 8) {
#pragma unroll
        for (int u = 0; u < 8; u++) {
            const int m = base + u;
            float2 p  = sxy[m];
            float  pz = sz[m];
            float dx = q.x - p.x;
            float dy = q.y - p.y;
            float dz = qz  - pz;
            float d2 = fmaf(dx, dx, fmaf(dy, dy, dz * dz));
            if (d2 <= R2) {
                if (cnt < NSAMPLE) vals[cnt] = d2;
                cnt++;
            }
        }
        if (__all_sync(0xffffffffu, cnt >= NSAMPLE)) break;
    }

    // Pad with the first member's value (cnt >= 1 always: self has d2 = 0)
    const float v0 = vals[0];
    for (int k = (cnt < NSAMPLE ? cnt : NSAMPLE); k < NSAMPLE; k++) vals[k] = v0;

    // Partial selection sort: 5 smallest ascending; accumulate ranks 1..4
    float acc = 0.0f;
#pragma unroll
    for (int i = 0; i < TOPK; i++) {
        int   mi = i;
        float mv = vals[i];
#pragma unroll
        for (int j = i + 1; j < NSAMPLE; j++) {
            if (vals[j] < mv) { mv = vals[j]; mi = j; }
        }
        vals[mi] = vals[i];
        vals[i]  = mv;
        if (i >= 1) {
            float ds = mv < EPS_ ? EPS_ : mv;
            acc += 0.1f - sqrtf(ds) * __expf(-ds * (1.0f / H2));
        }
    }

    // Deterministic in-block reduction: warp shuffle -> 4 lane-0 values
#pragma unroll
    for (int off = 16; off > 0; off >>= 1)
        acc += __shfl_down_sync(0xffffffffu, acc, off);

    __syncthreads();                 // done reading sz; safe to reuse as scratch
    const int wid  = threadIdx.x >> 5;
    const int lane = threadIdx.x & 31;
    if (lane == 0) sz[wid] = acc;
    __syncthreads();
    if (threadIdx.x == 0)
        g_partials[blockIdx.x] = (sz[0] + sz[1]) + (sz[2] + sz[3]);
}

__global__ void density_reduce(float* __restrict__ out, int nblocks, float inv_count) {
    __shared__ float red[256];
    float s = 0.0f;
    for (int i = threadIdx.x; i < nblocks; i += 256) s += g_partials[i];
    red[threadIdx.x] = s;
    __syncthreads();
#pragma unroll
    for (int st = 128; st > 0; st >>= 1) {
        if (threadIdx.x < st) red[threadIdx.x] += red[threadIdx.x + st];
        __syncthreads();
    }
    if (threadIdx.x == 0) out[0] = red[0] * inv_count;
}

extern "C" void kernel_launch(void* const* d_in, const int* in_sizes, int n_in,
                              void* d_out, int out_size) {
    const float* pred = (const float*)d_in[0];
    const int B = in_sizes[0] / (N_PTS * 3);
    const int nblocks = B * BLOCKS_PER_BATCH;

    density_main<<<nblocks, TPB>>>(pred);

    const float inv_count = 1.0f / (float)((long long)B * N_PTS * (TOPK - 1));
    density_reduce<<<1, 256>>>((float*)d_out, nblocks, inv_count);
}

// round 2
// speedup vs baseline: 4.1089x; 4.1089x over previous
#include <cuda_runtime.h>
#include <cuda_bf16.h>

#define N_PTS   4096
#define NSAMPLE 9
#define TOPK    5
#define R2      0.01f
#define H2      0.0144f
#define EPS_    1e-12f
#define MAXB    8
#define GRID_D  10
#define NCELL   1000     // 10^3
#define IMAX    0x7fffffff

#define TPB_B   128
#define BLK_PER_BATCH (N_PTS / TPB_B)   // 32

// scratch: cell-sorted points per batch
__device__ float2 g_sxy[MAXB * N_PTS];
__device__ float  g_sz [MAXB * N_PTS];
__device__ int    g_si [MAXB * N_PTS];
__device__ int    g_cs [MAXB * (NCELL + 1)];
__device__ float  g_partials[MAXB * BLK_PER_BATCH];

__device__ __forceinline__ int cell_of(float x, float y, float z) {
    int cx = min((int)(x * 10.0f), GRID_D - 1);
    int cy = min((int)(y * 10.0f), GRID_D - 1);
    int cz = min((int)(z * 10.0f), GRID_D - 1);
    return cz * 100 + cy * 10 + cx;
}

// ---------------- Kernel A: counting sort into cells (1 block / batch) ------
__global__ void __launch_bounds__(1024)
density_bin(const float* __restrict__ pred) {
    __shared__ int hist[NCELL];
    __shared__ int sbuf[2][1024];
    __shared__ int cstart[NCELL + 1];
    __shared__ int cursor[NCELL];
    __shared__ int pcell[N_PTS];

    const int b   = blockIdx.x;
    const int tid = threadIdx.x;
    const float* pb = pred + (size_t)b * N_PTS * 3;

    if (tid < NCELL) { hist[tid] = 0; cursor[tid] = 0; }
    __syncthreads();

    for (int i = tid; i < N_PTS; i += 1024) {
        float x = pb[i * 3 + 0], y = pb[i * 3 + 1], z = pb[i * 3 + 2];
        int c = cell_of(x, y, z);
        pcell[i] = c;
        atomicAdd(&hist[c], 1);
    }
    __syncthreads();

    // inclusive scan of 1024 slots (hist padded with 0)
    int v = (tid < NCELL) ? hist[tid] : 0;
    sbuf[0][tid] = v;
    __syncthreads();
    int cur = 0;
    for (int off = 1; off < 1024; off <<= 1) {
        int nv = sbuf[cur][tid];
        if (tid >= off) nv += sbuf[cur][tid - off];
        sbuf[1 - cur][tid] = nv;
        cur ^= 1;
        __syncthreads();
    }
    if (tid == 0) cstart[0] = 0;
    if (tid < NCELL) cstart[tid + 1] = sbuf[cur][tid];
    __syncthreads();

    for (int i = tid; i < N_PTS; i += 1024) {
        int c = pcell[i];
        int pos = cstart[c] + atomicAdd(&cursor[c], 1);
        float x = pb[i * 3 + 0], y = pb[i * 3 + 1], z = pb[i * 3 + 2];
        int g = b * N_PTS + pos;
        g_sxy[g] = make_float2(x, y);
        g_sz [g] = z;
        g_si [g] = i;
    }
    if (tid <= NCELL) g_cs[b * (NCELL + 1) + tid] = cstart[tid];
}

// ---------------- Kernel B: ball query + topk + loss (cell-coherent) -------
__global__ void __launch_bounds__(TPB_B)
density_group(int dummy) {
    extern __shared__ char smem[];
    float2* sxy = (float2*)smem;                       // 32 KB
    float*  szv = (float*)(smem + 32768);              // 16 KB
    int*    sid = (int*)  (smem + 49152);              // 16 KB
    int*    scs = (int*)  (smem + 65536);              // 4004 B

    const int b   = blockIdx.x / BLK_PER_BATCH;
    const int blk = blockIdx.x % BLK_PER_BATCH;
    const int goff = b * N_PTS;

    for (int i = threadIdx.x; i < N_PTS; i += TPB_B) {
        sxy[i] = g_sxy[goff + i];
        szv[i] = g_sz [goff + i];
        sid[i] = g_si [goff + i];
    }
    for (int i = threadIdx.x; i <= NCELL; i += TPB_B)
        scs[i] = g_cs[b * (NCELL + 1) + i];
    __syncthreads();

    const int t = blk * TPB_B + threadIdx.x;   // query = t-th point in sorted order
    const float2 q  = sxy[t];
    const float  qz = szv[t];

    int cx = min((int)(q.x * 10.0f), GRID_D - 1);
    int cy = min((int)(q.y * 10.0f), GRID_D - 1);
    int cz = min((int)(qz  * 10.0f), GRID_D - 1);
    const int x0 = max(cx - 1, 0), x1 = min(cx + 1, GRID_D - 1);
    const int y0 = max(cy - 1, 0), y1 = min(cy + 1, GRID_D - 1);
    const int z0 = max(cz - 1, 0), z1 = min(cz + 1, GRID_D - 1);

    // 9 smallest original indices among in-ball points (sorted ascending)
    int   idx9[NSAMPLE];
    float val9[NSAMPLE];
#pragma unroll
    for (int k = 0; k < NSAMPLE; k++) { idx9[k] = IMAX; val9[k] = 0.0f; }

    for (int zz = z0; zz <= z1; zz++) {
        for (int yy = y0; yy <= y1; yy++) {
            const int rowbase = zz * 100 + yy * 10;
            const int jb = scs[rowbase + x0];
            const int je = scs[rowbase + x1 + 1];
            for (int j = jb; j < je; j++) {
                float2 p  = sxy[j];
                float  pz = szv[j];
                float dx = q.x - p.x;
                float dy = q.y - p.y;
                float dz = qz  - pz;
                float d2 = fmaf(dx, dx, fmaf(dy, dy, dz * dz));
                if (d2 <= R2) {
                    int ci = sid[j];
                    if (ci < idx9[NSAMPLE - 1]) {
                        float cv = d2;
#pragma unroll
                        for (int k = 0; k < NSAMPLE; k++) {
                            if (ci < idx9[k]) {
                                int   ti = idx9[k]; idx9[k] = ci; ci = ti;
                                float tv = val9[k]; val9[k] = cv; cv = tv;
                            }
                        }
                    }
                }
            }
        }
    }

    // pad missing entries with first (smallest-index) member's value
    const float v0 = val9[0];   // self is always in-ball, so idx9[0] != IMAX
#pragma unroll
    for (int k = 1; k < NSAMPLE; k++)
        if (idx9[k] == IMAX) val9[k] = v0;

    // 5 smallest ascending; accumulate ranks 1..4
    float acc = 0.0f;
#pragma unroll
    for (int i = 0; i < TOPK; i++) {
        int   mi = i;
        float mv = val9[i];
#pragma unroll
        for (int j = i + 1; j < NSAMPLE; j++)
            if (val9[j] < mv) { mv = val9[j]; mi = j; }
        val9[mi] = val9[i];
        val9[i]  = mv;
        if (i >= 1) {
            float ds = mv < EPS_ ? EPS_ : mv;
            acc += 0.1f - sqrtf(ds) * __expf(-ds * (1.0f / H2));
        }
    }

    // deterministic block reduction
#pragma unroll
    for (int off = 16; off > 0; off >>= 1)
        acc += __shfl_down_sync(0xffffffffu, acc, off);

    __shared__ float red[TPB_B / 32];
    const int wid  = threadIdx.x >> 5;
    const int lane = threadIdx.x & 31;
    if (lane == 0) red[wid] = acc;
    __syncthreads();
    if (threadIdx.x == 0) {
        float s = 0.0f;
#pragma unroll
        for (int w = 0; w < TPB_B / 32; w++) s += red[w];
        g_partials[blockIdx.x] = s;
    }
}

__global__ void density_reduce(float* __restrict__ out, int nblocks, float inv_count) {
    __shared__ float red[256];
    float s = 0.0f;
    for (int i = threadIdx.x; i < nblocks; i += 256) s += g_partials[i];
    red[threadIdx.x] = s;
    __syncthreads();
#pragma unroll
    for (int st = 128; st > 0; st >>= 1) {
        if (threadIdx.x < st) red[threadIdx.x] += red[threadIdx.x + st];
        __syncthreads();
    }
    if (threadIdx.x == 0) out[0] = red[0] * inv_count;
}

extern "C" void kernel_launch(void* const* d_in, const int* in_sizes, int n_in,
                              void* d_out, int out_size) {
    const float* pred = (const float*)d_in[0];
    const int B = in_sizes[0] / (N_PTS * 3);
    const int nblocks = B * BLK_PER_BATCH;
    const int smem_b = 65536 + (NCELL + 1) * 4;

    cudaFuncSetAttribute(density_group,
                         cudaFuncAttributeMaxDynamicSharedMemorySize, smem_b);

    density_bin<<<B, 1024>>>(pred);
    density_group<<<nblocks, TPB_B, smem_b>>>(0);

    const float inv_count = 1.0f / (float)((long long)B * N_PTS * (TOPK - 1));
    density_reduce<<<1, 256>>>((float*)d_out, nblocks, inv_count);
}

// round 4
// speedup vs baseline: 4.7849x; 1.1645x over previous
#include <cuda_runtime.h>
#include <cuda_bf16.h>

#define N_PTS   4096
#define NSAMPLE 9
#define TOPK    5
#define R2      0.01f
#define H2      0.0144f
#define EPS_    1e-12f
#define MAXB    8
#define GRID_D  10
#define NCELL   1000
#define IMAX    0x7fffffff

#define TPB_B   128
#define BLK_PER_BATCH (N_PTS / TPB_B)   // 32

// cell-sorted points: xyz + original index in .w
__device__ float4 g_pts[MAXB * N_PTS];
__device__ int    g_cs [MAXB * (NCELL + 1)];
__device__ float  g_partials[MAXB * BLK_PER_BATCH];
__device__ unsigned int g_ticket;   // zero-init; reset by last block each launch

// ---------------- Kernel A: counting sort into cells (1 block / batch) ------
// dyn smem: stash float4[4096] (64K) | hist int[1024] (4K) | cstart int[1024] (4K) | wsum int[32]
#define BIN_SMEM (65536 + 4096 + 4096 + 128)

__global__ void __launch_bounds__(1024)
density_bin(const float* __restrict__ pred) {
    extern __shared__ char smem[];
    float4* stash  = (float4*)smem;
    int*    hist   = (int*)(smem + 65536);
    int*    cstart = (int*)(smem + 69632);
    int*    wsum   = (int*)(smem + 73728);

    const int b    = blockIdx.x;
    const int tid  = threadIdx.x;
    const int lane = tid & 31;
    const int wid  = tid >> 5;
    const float* pb = pred + (size_t)b * N_PTS * 3;

    if (tid < NCELL) hist[tid] = 0;
    __syncthreads();

    // pass 1: cell + histogram + smem stash (single gmem read of pred)
#pragma unroll
    for (int it = 0; it < N_PTS / 1024; it++) {
        const int i = it * 1024 + tid;
        float x = pb[i * 3 + 0], y = pb[i * 3 + 1], z = pb[i * 3 + 2];
        int cx = min((int)(x * 10.0f), GRID_D - 1);
        int cy = min((int)(y * 10.0f), GRID_D - 1);
        int cz = min((int)(z * 10.0f), GRID_D - 1);
        int c = cz * 100 + cy * 10 + cx;
        stash[i] = make_float4(x, y, z, __int_as_float(c));
        atomicAdd(&hist[c], 1);
    }
    __syncthreads();

    // warp-shuffle inclusive scan over 1024 slots (hist padded with 0)
    int x = (tid < NCELL) ? hist[tid] : 0;
#pragma unroll
    for (int off = 1; off < 32; off <<= 1) {
        int y = __shfl_up_sync(0xffffffffu, x, off);
        if (lane >= off) x += y;
    }
    if (lane == 31) wsum[wid] = x;
    __syncthreads();
    if (wid == 0) {
        int ws = wsum[lane];
        int wx = ws;
#pragma unroll
        for (int off = 1; off < 32; off <<= 1) {
            int y = __shfl_up_sync(0xffffffffu, wx, off);
            if (lane >= off) wx += y;
        }
        wsum[lane] = wx - ws;   // exclusive warp offset
    }
    __syncthreads();
    const int incl = x + wsum[wid];   // inclusive scan over cells [0..tid]

    // cstart[c] = exclusive prefix; incl at tid == cstart[tid+1]
    if (tid == 0) { cstart[0] = 0; g_cs[b * (NCELL + 1)] = 0; }
    if (tid < NCELL) {
        cstart[tid + 1] = incl;
        g_cs[b * (NCELL + 1) + tid + 1] = incl;   // FIXED: was g_cs[..+tid] (off by one)
        hist[tid] = 0;                            // reuse as cursor
    }
    __syncthreads();

    // pass 2: scatter from smem stash
#pragma unroll
    for (int it = 0; it < N_PTS / 1024; it++) {
        const int i = it * 1024 + tid;
        float4 f = stash[i];
        int c = __float_as_int(f.w);
        int pos = cstart[c] + atomicAdd(&hist[c], 1);
        g_pts[b * N_PTS + pos] = make_float4(f.x, f.y, f.z, __int_as_float(i));
    }
}

// ---------------- Kernel B: ball query + topk + loss + final reduce --------
// dyn smem: spts float4[4096] (64K) | scs int[1001] (4004 B)
#define GRP_SMEM (65536 + 4032)

__global__ void __launch_bounds__(TPB_B)
density_group(float* __restrict__ out, float inv_count) {
    extern __shared__ char smem[];
    float4* spts = (float4*)smem;
    int*    scs  = (int*)(smem + 65536);
    __shared__ float red[TPB_B / 32];
    __shared__ int   is_last;

    const int b    = blockIdx.x / BLK_PER_BATCH;
    const int blk  = blockIdx.x % BLK_PER_BATCH;
    const int goff = b * N_PTS;

    for (int i = threadIdx.x; i < N_PTS; i += TPB_B)
        spts[i] = g_pts[goff + i];
    for (int i = threadIdx.x; i <= NCELL; i += TPB_B)
        scs[i] = g_cs[b * (NCELL + 1) + i];
    __syncthreads();

    const int t = blk * TPB_B + threadIdx.x;     // query in sorted order
    const float4 q = spts[t];

    int cx = min((int)(q.x * 10.0f), GRID_D - 1);
    int cy = min((int)(q.y * 10.0f), GRID_D - 1);
    int cz = min((int)(q.z * 10.0f), GRID_D - 1);
    const int x0 = max(cx - 1, 0), x1 = min(cx + 1, GRID_D - 1);
    const int y0 = max(cy - 1, 0), y1 = min(cy + 1, GRID_D - 1);
    const int z0 = max(cz - 1, 0), z1 = min(cz + 1, GRID_D - 1);

    // 9 smallest original indices among in-ball points (ascending)
    int   idx9[NSAMPLE];
    float val9[NSAMPLE];
#pragma unroll
    for (int k = 0; k < NSAMPLE; k++) { idx9[k] = IMAX; val9[k] = 0.0f; }

    for (int zz = z0; zz <= z1; zz++) {
        for (int yy = y0; yy <= y1; yy++) {
            const int rowbase = zz * 100 + yy * 10;
            const int jb = scs[rowbase + x0];
            const int je = scs[rowbase + x1 + 1];
            for (int j = jb; j < je; j++) {
                float4 p = spts[j];                  // single LDS.128
                float dx = q.x - p.x;
                float dy = q.y - p.y;
                float dz = q.z - p.z;
                float d2 = fmaf(dx, dx, fmaf(dy, dy, dz * dz));
                if (d2 <= R2) {
                    int ci = __float_as_int(p.w);
                    if (ci < idx9[NSAMPLE - 1]) {
                        float cv = d2;
#pragma unroll
                        for (int k = 0; k < NSAMPLE; k++) {
                            if (ci < idx9[k]) {
                                int   ti = idx9[k]; idx9[k] = ci; ci = ti;
                                float tv = val9[k]; val9[k] = cv; cv = tv;
                            }
                        }
                    }
                }
            }
        }
    }

    const float v0 = val9[0];    // self always present
#pragma unroll
    for (int k = 1; k < NSAMPLE; k++)
        if (idx9[k] == IMAX) val9[k] = v0;

    float acc = 0.0f;
#pragma unroll
    for (int i = 0; i < TOPK; i++) {
        int   mi = i;
        float mv = val9[i];
#pragma unroll
        for (int j = i + 1; j < NSAMPLE; j++)
            if (val9[j] < mv) { mv = val9[j]; mi = j; }
        val9[mi] = val9[i];
        val9[i]  = mv;
        if (i >= 1) {
            float ds = mv < EPS_ ? EPS_ : mv;
            acc += 0.1f - sqrtf(ds) * __expf(-ds * (1.0f / H2));
        }
    }

    // deterministic block reduction
#pragma unroll
    for (int off = 16; off > 0; off >>= 1)
        acc += __shfl_down_sync(0xffffffffu, acc, off);
    const int wid  = threadIdx.x >> 5;
    const int lane = threadIdx.x & 31;
    if (lane == 0) red[wid] = acc;
    __syncthreads();
    if (threadIdx.x == 0) {
        float s = 0.0f;
#pragma unroll
        for (int w = 0; w < TPB_B / 32; w++) s += red[w];
        g_partials[blockIdx.x] = s;
        __threadfence();
        unsigned tk = atomicAdd(&g_ticket, 1u);
        is_last = (tk == gridDim.x - 1) ? 1 : 0;
    }
    __syncthreads();

    // last block: fixed-order final reduction (deterministic)
    if (is_last && threadIdx.x < 32) {
        const int nb = gridDim.x;
        float s = 0.0f;
        for (int i = lane; i < nb; i += 32) s += g_partials[i];
#pragma unroll
        for (int off = 16; off > 0; off >>= 1)
            s += __shfl_down_sync(0xffffffffu, s, off);
        if (lane == 0) {
            out[0] = s * inv_count;
            g_ticket = 0;   // reset for next launch / graph replay
        }
    }
}

extern "C" void kernel_launch(void* const* d_in, const int* in_sizes, int n_in,
                              void* d_out, int out_size) {
    const float* pred = (const float*)d_in[0];
    const int B = in_sizes[0] / (N_PTS * 3);
    const int nblocks = B * BLK_PER_BATCH;

    cudaFuncSetAttribute(density_bin,
                         cudaFuncAttributeMaxDynamicSharedMemorySize, BIN_SMEM);
    cudaFuncSetAttribute(density_group,
                         cudaFuncAttributeMaxDynamicSharedMemorySize, GRP_SMEM);

    density_bin<<<B, 1024, BIN_SMEM>>>(pred);

    const float inv_count = 1.0f / (float)((long long)B * N_PTS * (TOPK - 1));
    density_group<<<nblocks, TPB_B, GRP_SMEM>>>((float*)d_out, inv_count);
}

// round 5
// speedup vs baseline: 6.0762x; 1.2699x over previous
#include <cuda_runtime.h>
#include <cuda_bf16.h>

#define N_PTS   4096
#define NSAMPLE 9
#define TOPK    5
#define R2      0.01f
#define H2      0.0144f
#define EPS_    1e-12f
#define MAXB    8
#define GRID_D  10
#define NCELL   1000
#define IMAX    0x7fffffff

#define QPB     32                         // queries per block
#define TPB_G   (QPB * 4)                  // 4 threads per query = 128
#define GBLK_PER_BATCH (N_PTS / QPB)       // 128 blocks per batch

// cell-sorted points: xyz + original index in .w
__device__ float4 g_pts[MAXB * N_PTS];
__device__ int    g_cs [MAXB * (NCELL + 1)];
__device__ float  g_partials[MAXB * GBLK_PER_BATCH];
__device__ unsigned int g_ticket;   // zero-init; reset by last block each launch

// ---------------- Kernel A: counting sort into cells (1 block / batch) ------
// dyn smem: stash float4[4096] (64K) | hist int[1024] (4K) | cstart int[1024] (4K) | wsum int[32]
#define BIN_SMEM (65536 + 4096 + 4096 + 128)

__global__ void __launch_bounds__(1024)
density_bin(const float* __restrict__ pred) {
    extern __shared__ char smem[];
    float4* stash  = (float4*)smem;
    int*    hist   = (int*)(smem + 65536);
    int*    cstart = (int*)(smem + 69632);
    int*    wsum   = (int*)(smem + 73728);

    const int b    = blockIdx.x;
    const int tid  = threadIdx.x;
    const int lane = tid & 31;
    const int wid  = tid >> 5;
    const float* pb = pred + (size_t)b * N_PTS * 3;

    if (tid < NCELL) hist[tid] = 0;
    __syncthreads();

#pragma unroll
    for (int it = 0; it < N_PTS / 1024; it++) {
        const int i = it * 1024 + tid;
        float x = pb[i * 3 + 0], y = pb[i * 3 + 1], z = pb[i * 3 + 2];
        int cx = min((int)(x * 10.0f), GRID_D - 1);
        int cy = min((int)(y * 10.0f), GRID_D - 1);
        int cz = min((int)(z * 10.0f), GRID_D - 1);
        int c = cz * 100 + cy * 10 + cx;
        stash[i] = make_float4(x, y, z, __int_as_float(c));
        atomicAdd(&hist[c], 1);
    }
    __syncthreads();

    // warp-shuffle inclusive scan over 1024 slots
    int x = (tid < NCELL) ? hist[tid] : 0;
#pragma unroll
    for (int off = 1; off < 32; off <<= 1) {
        int y = __shfl_up_sync(0xffffffffu, x, off);
        if (lane >= off) x += y;
    }
    if (lane == 31) wsum[wid] = x;
    __syncthreads();
    if (wid == 0) {
        int ws = wsum[lane];
        int wx = ws;
#pragma unroll
        for (int off = 1; off < 32; off <<= 1) {
            int y = __shfl_up_sync(0xffffffffu, wx, off);
            if (lane >= off) wx += y;
        }
        wsum[lane] = wx - ws;
    }
    __syncthreads();
    const int incl = x + wsum[wid];

    if (tid == 0) { cstart[0] = 0; g_cs[b * (NCELL + 1)] = 0; }
    if (tid < NCELL) {
        cstart[tid + 1] = incl;
        g_cs[b * (NCELL + 1) + tid + 1] = incl;
        hist[tid] = 0;   // reuse as cursor
    }
    __syncthreads();

#pragma unroll
    for (int it = 0; it < N_PTS / 1024; it++) {
        const int i = it * 1024 + tid;
        float4 f = stash[i];
        int c = __float_as_int(f.w);
        int pos = cstart[c] + atomicAdd(&hist[c], 1);
        g_pts[b * N_PTS + pos] = make_float4(f.x, f.y, f.z, __int_as_float(i));
    }
}

// ---------------- Kernel B: quad-cooperative ball query + topk + loss ------
__global__ void __launch_bounds__(TPB_G)
density_group(float* __restrict__ out, float inv_count) {
    __shared__ float red[TPB_G / 32];
    __shared__ int   is_last;

    const int b    = blockIdx.x / GBLK_PER_BATCH;
    const int blk  = blockIdx.x % GBLK_PER_BATCH;
    const int goff = b * N_PTS;
    const int csoff = b * (NCELL + 1);

    const int tid    = threadIdx.x;
    const int lane   = tid & 31;
    const int tq     = tid & 3;        // lane within quad
    const int qlocal = tid >> 2;       // query within block (0..31)
    const int t      = blk * QPB + qlocal;   // query in sorted order

    const float4 q = __ldg(&g_pts[goff + t]);

    int cx = min((int)(q.x * 10.0f), GRID_D - 1);
    int cy = min((int)(q.y * 10.0f), GRID_D - 1);
    int cz = min((int)(q.z * 10.0f), GRID_D - 1);
    const int x0 = max(cx - 1, 0), x1 = min(cx + 1, GRID_D - 1);
    const int y0 = max(cy - 1, 0), y1 = min(cy + 1, GRID_D - 1);
    const int z0 = max(cz - 1, 0), z1 = min(cz + 1, GRID_D - 1);

    // per-lane: 9 smallest original indices among this lane's candidates
    int   idx9[NSAMPLE];
    float val9[NSAMPLE];
#pragma unroll
    for (int k = 0; k < NSAMPLE; k++) { idx9[k] = IMAX; val9[k] = 0.0f; }

    for (int zz = z0; zz <= z1; zz++) {
        for (int yy = y0; yy <= y1; yy++) {
            const int rowbase = zz * 100 + yy * 10;
            const int jb = __ldg(&g_cs[csoff + rowbase + x0]);
            const int je = __ldg(&g_cs[csoff + rowbase + x1 + 1]);
            for (int j = jb + tq; j < je; j += 4) {
                float4 p = __ldg(&g_pts[goff + j]);
                float dx = q.x - p.x;
                float dy = q.y - p.y;
                float dz = q.z - p.z;
                float d2 = fmaf(dx, dx, fmaf(dy, dy, dz * dz));
                if (d2 <= R2) {
                    int ci = __float_as_int(p.w);
                    if (ci < idx9[NSAMPLE - 1]) {
                        float cv = d2;
#pragma unroll
                        for (int k = 0; k < NSAMPLE; k++) {
                            if (ci < idx9[k]) {
                                int   ti = idx9[k]; idx9[k] = ci; ci = ti;
                                float tv = val9[k]; val9[k] = cv; cv = tv;
                            }
                        }
                    }
                }
            }
        }
    }

    // quad merge: 9 pop-min rounds over the 4 sorted per-lane lists.
    // Indices are unique, so exactly one lane pops per round (or none at IMAX).
    int   mi9[NSAMPLE];
    float m9 [NSAMPLE];
#pragma unroll
    for (int k = 0; k < NSAMPLE; k++) {
        int   bi = idx9[0];
        float bv = val9[0];
        int   oi = __shfl_xor_sync(0xffffffffu, bi, 1);
        float ov = __shfl_xor_sync(0xffffffffu, bv, 1);
        if (oi < bi) { bi = oi; bv = ov; }
        oi = __shfl_xor_sync(0xffffffffu, bi, 2);
        ov = __shfl_xor_sync(0xffffffffu, bv, 2);
        if (oi < bi) { bi = oi; bv = ov; }
        mi9[k] = bi;
        m9 [k] = bv;
        if (idx9[0] == bi && bi != IMAX) {   // this lane pops its head
#pragma unroll
            for (int s = 0; s < NSAMPLE - 1; s++) {
                idx9[s] = idx9[s + 1];
                val9[s] = val9[s + 1];
            }
            idx9[NSAMPLE - 1] = IMAX;
        }
    }

    // epilogue on quad leader only
    float acc = 0.0f;
    if (tq == 0) {
        const float v0 = m9[0];              // self always in-ball => mi9[0] != IMAX
#pragma unroll
        for (int k = 1; k < NSAMPLE; k++)
            if (mi9[k] == IMAX) m9[k] = v0;

#pragma unroll
        for (int i = 0; i < TOPK; i++) {
            int   mi = i;
            float mv = m9[i];
#pragma unroll
            for (int j = i + 1; j < NSAMPLE; j++)
                if (m9[j] < mv) { mv = m9[j]; mi = j; }
            m9[mi] = m9[i];
            m9[i]  = mv;
            if (i >= 1) {
                float ds = mv < EPS_ ? EPS_ : mv;
                acc += 0.1f - sqrtf(ds) * __expf(-ds * (1.0f / H2));
            }
        }
    }

    // deterministic block reduction (non-leader lanes contribute 0)
#pragma unroll
    for (int off = 16; off > 0; off >>= 1)
        acc += __shfl_down_sync(0xffffffffu, acc, off);
    const int wid = tid >> 5;
    if (lane == 0) red[wid] = acc;
    __syncthreads();
    if (tid == 0) {
        float s = 0.0f;
#pragma unroll
        for (int w = 0; w < TPB_G / 32; w++) s += red[w];
        g_partials[blockIdx.x] = s;
        __threadfence();
        unsigned tk = atomicAdd(&g_ticket, 1u);
        is_last = (tk == gridDim.x - 1) ? 1 : 0;
    }
    __syncthreads();

    if (is_last && tid < 32) {
        const int nb = gridDim.x;
        float s = 0.0f;
        for (int i = lane; i < nb; i += 32) s += g_partials[i];
#pragma unroll
        for (int off = 16; off > 0; off >>= 1)
            s += __shfl_down_sync(0xffffffffu, s, off);
        if (lane == 0) {
            out[0] = s * inv_count;
            g_ticket = 0;
        }
    }
}

extern "C" void kernel_launch(void* const* d_in, const int* in_sizes, int n_in,
                              void* d_out, int out_size) {
    const float* pred = (const float*)d_in[0];
    const int B = in_sizes[0] / (N_PTS * 3);
    const int nblocks = B * GBLK_PER_BATCH;

    cudaFuncSetAttribute(density_bin,
                         cudaFuncAttributeMaxDynamicSharedMemorySize, BIN_SMEM);

    density_bin<<<B, 1024, BIN_SMEM>>>(pred);

    const float inv_count = 1.0f / (float)((long long)B * N_PTS * (TOPK - 1));
    density_group<<<nblocks, TPB_G>>>((float*)d_out, inv_count);
}